// round 7
// baseline (speedup 1.0000x reference)
#include <cuda_runtime.h>
#include <cuda_bf16.h>
#include <cstdint>

// ---------------------------------------------------------------------------
// Problem constants
// ---------------------------------------------------------------------------
#define D       64
#define KTOT    2048
#define NROWS   65536
#define KDIM    192                  // GEMM K: [X0,X0,X1] x [E0,E1,E0]
#define M_BLK   256                  // rows per block (32 per warp)
#define NSUB    64
#define NSUBS   (KTOT / NSUB)        // 32
#define NBLOCKS (NROWS / M_BLK)      // 256
// |approx - exact| <= 3*2^-18*||x||*||e|| <= ~6.9e-4; x2 margin -> 2.5e-3
#define THRESH  2.5e-3f

// Output layout (concatenated fp32)
#define OFF_IDX  ((size_t)NROWS * D)
#define OFF_FLAT ((size_t)NROWS * D + NROWS)

// smem layout (bytes); row stride 400B for conflict-free ldmatrix
#define SA_BYTES   400
#define SM_A       0
#define SM_B0      (M_BLK * SA_BYTES)               // 102400
#define SM_B1      (SM_B0 + 64 * SA_BYTES)          // 128000
#define SM_NH0     (SM_B1 + 64 * SA_BYTES)          // 153600
#define SM_NH1     (SM_NH0 + 256)                   // 153856
#define SMEM_TOTAL (SM_NH1 + 256)                   // 154112

// ---------------------------------------------------------------------------
// Device scratch (no cudaMalloc allowed)
// ---------------------------------------------------------------------------
__device__ unsigned g_B[KTOT * (KDIM / 2)];   // B' packed bf16x2, 768 KB (L2-resident)
__device__ float    g_nh[KTOT];               // -0.5*||e_k||^2
__device__ int      g_bi[NROWS];
__device__ int      g_rlist[NROWS];
__device__ int      g_rcnt;

// ---------------------------------------------------------------------------
// PTX helpers (all baseline sm_80+, safe for compute_103)
// ---------------------------------------------------------------------------
__device__ __forceinline__ uint32_t smem_u32(const void* p) {
    uint32_t a;
    asm("{ .reg .u64 t; cvta.to.shared.u64 t, %1; cvt.u32.u64 %0, t; }" : "=r"(a) : "l"(p));
    return a;
}
__device__ __forceinline__ void cpa16(uint32_t dst, const void* src) {
    asm volatile("cp.async.cg.shared.global [%0], [%1], 16;" :: "r"(dst), "l"(src));
}
#define CP_COMMIT() asm volatile("cp.async.commit_group;" ::: "memory")
#define CP_WAIT0()  asm volatile("cp.async.wait_group 0;" ::: "memory")

#define LDSM4(r0, r1, r2, r3, addr)                                           \
    asm volatile("ldmatrix.sync.aligned.m8n8.x4.shared.b16 {%0,%1,%2,%3}, [%4];" \
                 : "=r"(r0), "=r"(r1), "=r"(r2), "=r"(r3) : "r"(addr))

#define MMA16816(c, a0, a1, a2, a3, b0, b1)                                   \
    asm volatile("mma.sync.aligned.m16n8k16.row.col.f32.bf16.bf16.f32 "       \
                 "{%0,%1,%2,%3}, {%4,%5,%6,%7}, {%8,%9}, {%0,%1,%2,%3};"      \
                 : "+f"((c)[0]), "+f"((c)[1]), "+f"((c)[2]), "+f"((c)[3])     \
                 : "r"(a0), "r"(a1), "r"(a2), "r"(a3), "r"(b0), "r"(b1))

// ---------------------------------------------------------------------------
// Exact 2-way bf16 split: x = f0 + f1 + O(2^-18 |x|)
// ---------------------------------------------------------------------------
__device__ __forceinline__ void split2(float x, unsigned short& s0, unsigned short& s1) {
    __nv_bfloat16 h0 = __float2bfloat16_rn(x);
    float r = x - __bfloat162float(h0);        // exact (Sterbenz)
    __nv_bfloat16 h1 = __float2bfloat16_rn(r);
    s0 = __bfloat16_as_ushort(h0);
    s1 = __bfloat16_as_ushort(h1);
}

// Prep: B' rows = [E0 | E1 | E0]
__global__ void vq_split_e(const float* __restrict__ emb) {
    int i = blockIdx.x * blockDim.x + threadIdx.x;   // KTOT*32 threads
    float2 v = reinterpret_cast<const float2*>(emb)[i];
    unsigned short a0, a1, b0, b1;
    split2(v.x, a0, a1);
    split2(v.y, b0, b1);
    unsigned p0 = (unsigned)a0 | ((unsigned)b0 << 16);
    unsigned p1 = (unsigned)a1 | ((unsigned)b1 << 16);
    int k = i >> 5, d2 = i & 31;
    unsigned* base = g_B + (size_t)k * 96;
    base[d2]      = p0;
    base[32 + d2] = p1;
    base[64 + d2] = p0;
}

// Prep: nh[k] = -0.5*||e_k||^2 ; also reset rescue counter
__global__ void vq_nh_kernel(const float* __restrict__ emb) {
    int k = blockIdx.x * blockDim.x + threadIdx.x;
    if (k == 0) g_rcnt = 0;
    if (k >= KTOT) return;
    const float4* e4 = reinterpret_cast<const float4*>(emb + (size_t)k * D);
    float s0 = 0.f, s1 = 0.f, s2 = 0.f, s3 = 0.f;
#pragma unroll
    for (int i = 0; i < D / 4; i++) {
        float4 v = e4[i];
        s0 = fmaf(v.x, v.x, s0);
        s1 = fmaf(v.y, v.y, s1);
        s2 = fmaf(v.z, v.z, s2);
        s3 = fmaf(v.w, v.w, s3);
    }
    g_nh[k] = -0.5f * ((s0 + s1) + (s2 + s3));
}

// ---------------------------------------------------------------------------
// top-2 update (ascending idx order per thread; strict > => lowest idx wins)
// ---------------------------------------------------------------------------
__device__ __forceinline__ void upd(float& b1, float& b2, int& i1, float v, int idx) {
    if (v > b1) { b2 = b1; b1 = v; i1 = idx; }
    else        { b2 = fmaxf(b2, v); }
}
__device__ __forceinline__ void mergepair(float& b1, float& b2, int& i1, unsigned m) {
    float ob1 = __shfl_xor_sync(0xffffffffu, b1, m);
    float ob2 = __shfl_xor_sync(0xffffffffu, b2, m);
    int   oi1 = __shfl_xor_sync(0xffffffffu, i1, m);
    if (ob1 > b1 || (ob1 == b1 && oi1 < i1)) { b2 = fmaxf(b1, ob2); b1 = ob1; i1 = oi1; }
    else                                     { b2 = fmaxf(b2, ob1); }
}

// ---------------------------------------------------------------------------
// Main kernel: 256 rows/block, 8 warps, 32 rows/warp (2 m-tiles share each
// B fragment). x is split to bf16 planes in-kernel.
// ---------------------------------------------------------------------------
__global__ void __launch_bounds__(256, 1) vq_mma_kernel(const float* __restrict__ inp) {
    extern __shared__ __align__(16) char smem[];
    const uint32_t SB  = smem_u32(smem);
    const int tid  = threadIdx.x;
    const int lane = tid & 31;
    const int wid  = tid >> 5;
    const int row0blk = blockIdx.x * M_BLK;

    const uint32_t smA = SB + SM_A;
    const uint32_t smB[2] = { SB + SM_B0, SB + SM_B1 };
    float* nhbuf[2] = { (float*)(smem + SM_NH0), (float*)(smem + SM_NH1) };

    // ---- prologue: prefetch B subtile 0 (async), then split A into smem ----
    {
        const char* gB = (const char*)g_B;
#pragma unroll
        for (int i = tid; i < 64 * 24; i += 256) {
            int r = i / 24, c = i - r * 24;
            cpa16(smB[0] + r * SA_BYTES + c * 16, gB + (size_t)r * 384 + c * 16);
        }
        if (tid < 64) nhbuf[0][tid] = g_nh[tid];
        CP_COMMIT();

        const float2* xin = reinterpret_cast<const float2*>(inp + (size_t)row0blk * D);
#pragma unroll
        for (int i = tid; i < M_BLK * 32; i += 256) {
            int r = i >> 5, d2 = i & 31;
            float2 v = xin[i];
            unsigned short a0, a1, b0, b1;
            split2(v.x, a0, a1);
            split2(v.y, b0, b1);
            unsigned p0 = (unsigned)a0 | ((unsigned)b0 << 16);
            unsigned p1 = (unsigned)a1 | ((unsigned)b1 << 16);
            unsigned* rowp = reinterpret_cast<unsigned*>(smem + SM_A + r * SA_BYTES);
            rowp[d2]      = p0;
            rowp[32 + d2] = p0;
            rowp[64 + d2] = p1;
        }
        CP_WAIT0();
        __syncthreads();
    }

    const uint32_t aAddr0 = smA + (wid * 32 + (lane & 15)) * SA_BYTES + (lane >> 4) * 16;
    const uint32_t aAddr1 = aAddr0 + 16 * SA_BYTES;
    const int q       = lane >> 3;
    const int brow    = ((q >> 1) * 8) + (lane & 7);
    const uint32_t bk = (q & 1) * 16;

    float b1r[4], b2r[4];
    int   i1r[4];
#pragma unroll
    for (int r = 0; r < 4; r++) { b1r[r] = b2r[r] = -3.402823466e+38f; i1r[r] = 0; }

    for (int s = 0; s < NSUBS; s++) {
        const int buf = s & 1;
        if (s + 1 < NSUBS) {
            const char* gB = (const char*)(g_B + (size_t)(s + 1) * 64 * 96);
#pragma unroll
            for (int i = tid; i < 64 * 24; i += 256) {
                int r = i / 24, c = i - r * 24;
                cpa16(smB[buf ^ 1] + r * SA_BYTES + c * 16, gB + (size_t)r * 384 + c * 16);
            }
            if (tid < 64) nhbuf[buf ^ 1][tid] = g_nh[(s + 1) * 64 + tid];
            CP_COMMIT();
        }

        float c[2][8][4];
#pragma unroll
        for (int mt = 0; mt < 2; mt++)
#pragma unroll
            for (int j = 0; j < 8; j++)
                c[mt][j][0] = c[mt][j][1] = c[mt][j][2] = c[mt][j][3] = 0.f;

        const uint32_t bb = smB[buf];
#pragma unroll
        for (int k = 0; k < 12; k++) {
            uint32_t a0, a1, a2, a3, a4, a5, a6, a7;
            LDSM4(a0, a1, a2, a3, aAddr0 + k * 32);
            LDSM4(a4, a5, a6, a7, aAddr1 + k * 32);
#pragma unroll
            for (int t = 0; t < 4; t++) {
                uint32_t r0, r1, r2, r3;
                LDSM4(r0, r1, r2, r3, bb + (t * 16 + brow) * SA_BYTES + bk + k * 32);
                MMA16816(c[0][2 * t],     a0, a1, a2, a3, r0, r1);
                MMA16816(c[0][2 * t + 1], a0, a1, a2, a3, r2, r3);
                MMA16816(c[1][2 * t],     a4, a5, a6, a7, r0, r1);
                MMA16816(c[1][2 * t + 1], a4, a5, a6, a7, r2, r3);
            }
        }

        const float* snh = nhbuf[buf];
        const int cb = s * NSUB;
#pragma unroll
        for (int j = 0; j < 8; j++) {
            const int lc = j * 8 + 2 * (lane & 3);
            const float nh0 = snh[lc], nh1 = snh[lc + 1];
            const int gi = cb + lc;
            upd(b1r[0], b2r[0], i1r[0], c[0][j][0] + nh0, gi);
            upd(b1r[0], b2r[0], i1r[0], c[0][j][1] + nh1, gi + 1);
            upd(b1r[1], b2r[1], i1r[1], c[0][j][2] + nh0, gi);
            upd(b1r[1], b2r[1], i1r[1], c[0][j][3] + nh1, gi + 1);
            upd(b1r[2], b2r[2], i1r[2], c[1][j][0] + nh0, gi);
            upd(b1r[2], b2r[2], i1r[2], c[1][j][1] + nh1, gi + 1);
            upd(b1r[3], b2r[3], i1r[3], c[1][j][2] + nh0, gi);
            upd(b1r[3], b2r[3], i1r[3], c[1][j][3] + nh1, gi + 1);
        }

        if (s + 1 < NSUBS) {
            CP_WAIT0();
            __syncthreads();
        }
    }

#pragma unroll
    for (int r = 0; r < 4; r++) {
        mergepair(b1r[r], b2r[r], i1r[r], 1);
        mergepair(b1r[r], b2r[r], i1r[r], 2);
    }

    if ((lane & 3) == 0) {
        const int base = row0blk + wid * 32 + (lane >> 2);
        const int rofs[4] = { 0, 8, 16, 24 };
#pragma unroll
        for (int r = 0; r < 4; r++) {
            const int row = base + rofs[r];
            g_bi[row] = i1r[r];
            if (b1r[r] - b2r[r] < THRESH) {
                int p = atomicAdd(&g_rcnt, 1);
                g_rlist[p] = row;
            }
        }
    }
}

// ---------------------------------------------------------------------------
// Rescue: exact fp32 full rescan for flagged rows. Block-tiled: thread = one
// flagged row, 64-code embedding tiles staged in smem (broadcast reads).
// Fixed 64-block grid loops the flag list (graph-safe).
// ---------------------------------------------------------------------------
#define RES_BLOCKS 64
__global__ void __launch_bounds__(256)
vq_rescue_kernel(const float* __restrict__ inp, const float* __restrict__ emb) {
    __shared__ __align__(16) float se[64 * D];   // 16 KB tile
    __shared__ float snh[64];

    const int tid = threadIdx.x;
    const int cnt = g_rcnt;

    for (int base = blockIdx.x * 256; base < cnt; base += RES_BLOCKS * 256) {
        const int  li    = base + tid;
        const bool valid = (li < cnt);
        const int  row   = valid ? g_rlist[li] : 0;

        float4 x[16];
        const float4* xr = reinterpret_cast<const float4*>(inp + (size_t)row * D);
#pragma unroll
        for (int j = 0; j < 16; j++) x[j] = xr[j];

        float best = -3.402823466e+38f;
        int   bi   = 0;

        for (int k0 = 0; k0 < KTOT; k0 += 64) {
            __syncthreads();
            const float4* eg = reinterpret_cast<const float4*>(emb + (size_t)k0 * D);
            float4* s4 = reinterpret_cast<float4*>(se);
#pragma unroll
            for (int i = tid; i < 64 * (D / 4); i += 256) s4[i] = eg[i];
            if (tid < 64) snh[tid] = g_nh[k0 + tid];
            __syncthreads();

#pragma unroll 2
            for (int k = 0; k < 64; k++) {
                const float4* ek = reinterpret_cast<const float4*>(se + k * D);
                float d0 = 0.f, d1 = 0.f, d2 = 0.f, d3 = 0.f;
#pragma unroll
                for (int j = 0; j < 16; j++) {
                    float4 e = ek[j];
                    d0 = fmaf(x[j].x, e.x, d0);
                    d1 = fmaf(x[j].y, e.y, d1);
                    d2 = fmaf(x[j].z, e.z, d2);
                    d3 = fmaf(x[j].w, e.w, d3);
                }
                float sc = ((d0 + d1) + (d2 + d3)) + snh[k];
                if (sc > best) { best = sc; bi = k0 + k; }  // ascending k
            }
        }
        if (valid) g_bi[row] = bi;
        __syncthreads();
    }
}

// ---------------------------------------------------------------------------
// Combine: emit all three outputs, fully coalesced (16 threads per row)
// ---------------------------------------------------------------------------
__global__ void __launch_bounds__(256)
vq_combine_kernel(const float* __restrict__ inp,
                  const float* __restrict__ emb,
                  float* __restrict__ out) {
    const int t   = blockIdx.x * blockDim.x + threadIdx.x;   // NROWS*16
    const int row = t >> 4;
    const int c   = t & 15;
    const int bi  = g_bi[row];

    const float4 qv = reinterpret_cast<const float4*>(emb + (size_t)bi * D)[c];
    reinterpret_cast<float4*>(out + (size_t)row * D)[c] = qv;

    const float4 xi = reinterpret_cast<const float4*>(inp + (size_t)row * D)[c];
    reinterpret_cast<float4*>(out + OFF_FLAT + (size_t)row * D)[c] = xi;

    if (c == 0) out[OFF_IDX + row] = (float)bi;
}

// ---------------------------------------------------------------------------
extern "C" void kernel_launch(void* const* d_in, const int* in_sizes, int n_in,
                              void* d_out, int out_size) {
    const float* inp = (const float*)d_in[0];   // [64,32,32,64] fp32
    const float* emb = (const float*)d_in[1];   // [2048,64]     fp32
    float* out = (float*)d_out;

    static int smem_set = 0;
    if (!smem_set) {
        cudaFuncSetAttribute(vq_mma_kernel,
                             cudaFuncAttributeMaxDynamicSharedMemorySize, SMEM_TOTAL);
        smem_set = 1;
    }

    vq_split_e<<<KTOT * 32 / 256, 256>>>(emb);
    vq_nh_kernel<<<(KTOT + 255) / 256, 256>>>(emb);
    vq_mma_kernel<<<NBLOCKS, 256, SMEM_TOTAL>>>(inp);
    vq_rescue_kernel<<<RES_BLOCKS, 256>>>(inp, emb);
    vq_combine_kernel<<<NROWS * 16 / 256, 256>>>(inp, emb, out);
}

// round 8
// speedup vs baseline: 2.1699x; 2.1699x over previous
#include <cuda_runtime.h>
#include <cuda_bf16.h>
#include <cstdint>

// ---------------------------------------------------------------------------
// Problem constants
// ---------------------------------------------------------------------------
#define D       64
#define KTOT    2048
#define NROWS   65536
#define KDIM    192                  // GEMM K: [X0,X0,X1] x [E0,E1,E0]
#define M_BLK   256                  // rows per block (32 per warp)
#define NSUB    64
#define NSUBS   (KTOT / NSUB)        // 32
#define NBLOCKS (NROWS / M_BLK)      // 256
// |approx - exact| <= ~2*3*2^-18*||x||*||e|| ; safe margin
#define THRESH  2.5e-3f

// Output layout (concatenated fp32)
#define OFF_IDX  ((size_t)NROWS * D)
#define OFF_FLAT ((size_t)NROWS * D + NROWS)

// smem layout (bytes); row stride 400B for conflict-free ldmatrix
#define SA_BYTES   400
#define SM_A       0
#define SM_B0      (M_BLK * SA_BYTES)               // 102400
#define SM_B1      (SM_B0 + 64 * SA_BYTES)          // 128000
#define SM_NH0     (SM_B1 + 64 * SA_BYTES)          // 153600
#define SM_NH1     (SM_NH0 + 256)                   // 153856
#define SMEM_TOTAL (SM_NH1 + 256)                   // 154112

// ---------------------------------------------------------------------------
// Device scratch (no cudaMalloc allowed)
// ---------------------------------------------------------------------------
__device__ unsigned g_B[KTOT * (KDIM / 2)];    // B' packed bf16x2 (L2-resident)
__device__ float    g_nh[KTOT];                // -0.5*||e_k||^2
__device__ int      g_bi[NROWS];
__device__ int      g_rlist[NROWS];
__device__ int      g_rcnt;
__device__ unsigned long long g_bm[NROWS];     // packed (score,~idx) for rescue

// ---------------------------------------------------------------------------
// PTX helpers (all baseline sm_80+, safe for compute_103)
// ---------------------------------------------------------------------------
__device__ __forceinline__ uint32_t smem_u32(const void* p) {
    uint32_t a;
    asm("{ .reg .u64 t; cvta.to.shared.u64 t, %1; cvt.u32.u64 %0, t; }" : "=r"(a) : "l"(p));
    return a;
}
__device__ __forceinline__ void cpa16(uint32_t dst, const void* src) {
    asm volatile("cp.async.cg.shared.global [%0], [%1], 16;" :: "r"(dst), "l"(src));
}
#define CP_COMMIT() asm volatile("cp.async.commit_group;" ::: "memory")
#define CP_WAIT0()  asm volatile("cp.async.wait_group 0;" ::: "memory")

#define LDSM4(r0, r1, r2, r3, addr)                                           \
    asm volatile("ldmatrix.sync.aligned.m8n8.x4.shared.b16 {%0,%1,%2,%3}, [%4];" \
                 : "=r"(r0), "=r"(r1), "=r"(r2), "=r"(r3) : "r"(addr))

#define MMA16816(c, a0, a1, a2, a3, b0, b1)                                   \
    asm volatile("mma.sync.aligned.m16n8k16.row.col.f32.bf16.bf16.f32 "       \
                 "{%0,%1,%2,%3}, {%4,%5,%6,%7}, {%8,%9}, {%0,%1,%2,%3};"      \
                 : "+f"((c)[0]), "+f"((c)[1]), "+f"((c)[2]), "+f"((c)[3])     \
                 : "r"(a0), "r"(a1), "r"(a2), "r"(a3), "r"(b0), "r"(b1))

// ---------------------------------------------------------------------------
// Exact 2-way bf16 split: x = f0 + f1 + O(2^-18 |x|)
// ---------------------------------------------------------------------------
__device__ __forceinline__ void split2(float x, unsigned short& s0, unsigned short& s1) {
    __nv_bfloat16 h0 = __float2bfloat16_rn(x);
    float r = x - __bfloat162float(h0);        // exact (Sterbenz)
    __nv_bfloat16 h1 = __float2bfloat16_rn(r);
    s0 = __bfloat16_as_ushort(h0);
    s1 = __bfloat16_as_ushort(h1);
}

// Prep: B' rows = [E0 | E1 | E0]
__global__ void vq_split_e(const float* __restrict__ emb) {
    int i = blockIdx.x * blockDim.x + threadIdx.x;   // KTOT*32 threads
    float2 v = reinterpret_cast<const float2*>(emb)[i];
    unsigned short a0, a1, b0, b1;
    split2(v.x, a0, a1);
    split2(v.y, b0, b1);
    unsigned p0 = (unsigned)a0 | ((unsigned)b0 << 16);
    unsigned p1 = (unsigned)a1 | ((unsigned)b1 << 16);
    int k = i >> 5, d2 = i & 31;
    unsigned* base = g_B + (size_t)k * 96;
    base[d2]      = p0;
    base[32 + d2] = p1;
    base[64 + d2] = p0;
}

// Prep: nh[k] = -0.5*||e_k||^2 ; also reset rescue counter
__global__ void vq_nh_kernel(const float* __restrict__ emb) {
    int k = blockIdx.x * blockDim.x + threadIdx.x;
    if (k == 0) g_rcnt = 0;
    if (k >= KTOT) return;
    const float4* e4 = reinterpret_cast<const float4*>(emb + (size_t)k * D);
    float s0 = 0.f, s1 = 0.f, s2 = 0.f, s3 = 0.f;
#pragma unroll
    for (int i = 0; i < D / 4; i++) {
        float4 v = e4[i];
        s0 = fmaf(v.x, v.x, s0);
        s1 = fmaf(v.y, v.y, s1);
        s2 = fmaf(v.z, v.z, s2);
        s3 = fmaf(v.w, v.w, s3);
    }
    g_nh[k] = -0.5f * ((s0 + s1) + (s2 + s3));
}

// ---------------------------------------------------------------------------
// top-2 update (ascending idx order per thread; strict > => lowest idx wins)
// ---------------------------------------------------------------------------
__device__ __forceinline__ void upd(float& b1, float& b2, int& i1, float v, int idx) {
    if (v > b1) { b2 = b1; b1 = v; i1 = idx; }
    else        { b2 = fmaxf(b2, v); }
}
__device__ __forceinline__ void mergepair(float& b1, float& b2, int& i1, unsigned m) {
    float ob1 = __shfl_xor_sync(0xffffffffu, b1, m);
    float ob2 = __shfl_xor_sync(0xffffffffu, b2, m);
    int   oi1 = __shfl_xor_sync(0xffffffffu, i1, m);
    if (ob1 > b1 || (ob1 == b1 && oi1 < i1)) { b2 = fmaxf(b1, ob2); b1 = ob1; i1 = oi1; }
    else                                     { b2 = fmaxf(b2, ob1); }
}

// ---------------------------------------------------------------------------
// Main kernel: 256 rows/block, 8 warps, 32 rows/warp (2 m-tiles share each
// B fragment). x is split to bf16 planes in-kernel.
// ---------------------------------------------------------------------------
__global__ void __launch_bounds__(256, 1) vq_mma_kernel(const float* __restrict__ inp) {
    extern __shared__ __align__(16) char smem[];
    const uint32_t SB  = smem_u32(smem);
    const int tid  = threadIdx.x;
    const int lane = tid & 31;
    const int wid  = tid >> 5;
    const int row0blk = blockIdx.x * M_BLK;

    const uint32_t smA = SB + SM_A;
    const uint32_t smB[2] = { SB + SM_B0, SB + SM_B1 };
    float* nhbuf[2] = { (float*)(smem + SM_NH0), (float*)(smem + SM_NH1) };

    // ---- prologue: prefetch B subtile 0 (async), then split A into smem ----
    {
        const char* gB = (const char*)g_B;
#pragma unroll
        for (int i = tid; i < 64 * 24; i += 256) {
            int r = i / 24, c = i - r * 24;
            cpa16(smB[0] + r * SA_BYTES + c * 16, gB + (size_t)r * 384 + c * 16);
        }
        if (tid < 64) nhbuf[0][tid] = g_nh[tid];
        CP_COMMIT();

        const float2* xin = reinterpret_cast<const float2*>(inp + (size_t)row0blk * D);
#pragma unroll
        for (int i = tid; i < M_BLK * 32; i += 256) {
            int r = i >> 5, d2 = i & 31;
            float2 v = xin[i];
            unsigned short a0, a1, b0, b1;
            split2(v.x, a0, a1);
            split2(v.y, b0, b1);
            unsigned p0 = (unsigned)a0 | ((unsigned)b0 << 16);
            unsigned p1 = (unsigned)a1 | ((unsigned)b1 << 16);
            unsigned* rowp = reinterpret_cast<unsigned*>(smem + SM_A + r * SA_BYTES);
            rowp[d2]      = p0;
            rowp[32 + d2] = p0;
            rowp[64 + d2] = p1;
        }
        CP_WAIT0();
        __syncthreads();
    }

    const uint32_t aAddr0 = smA + (wid * 32 + (lane & 15)) * SA_BYTES + (lane >> 4) * 16;
    const uint32_t aAddr1 = aAddr0 + 16 * SA_BYTES;
    const int q       = lane >> 3;
    const int brow    = ((q >> 1) * 8) + (lane & 7);
    const uint32_t bk = (q & 1) * 16;

    float b1r[4], b2r[4];
    int   i1r[4];
#pragma unroll
    for (int r = 0; r < 4; r++) { b1r[r] = b2r[r] = -3.402823466e+38f; i1r[r] = 0; }

    for (int s = 0; s < NSUBS; s++) {
        const int buf = s & 1;
        if (s + 1 < NSUBS) {
            const char* gB = (const char*)(g_B + (size_t)(s + 1) * 64 * 96);
#pragma unroll
            for (int i = tid; i < 64 * 24; i += 256) {
                int r = i / 24, c = i - r * 24;
                cpa16(smB[buf ^ 1] + r * SA_BYTES + c * 16, gB + (size_t)r * 384 + c * 16);
            }
            if (tid < 64) nhbuf[buf ^ 1][tid] = g_nh[(s + 1) * 64 + tid];
            CP_COMMIT();
        }

        float c[2][8][4];
#pragma unroll
        for (int mt = 0; mt < 2; mt++)
#pragma unroll
            for (int j = 0; j < 8; j++)
                c[mt][j][0] = c[mt][j][1] = c[mt][j][2] = c[mt][j][3] = 0.f;

        const uint32_t bb = smB[buf];
#pragma unroll
        for (int k = 0; k < 12; k++) {
            uint32_t a0, a1, a2, a3, a4, a5, a6, a7;
            LDSM4(a0, a1, a2, a3, aAddr0 + k * 32);
            LDSM4(a4, a5, a6, a7, aAddr1 + k * 32);
#pragma unroll
            for (int t = 0; t < 4; t++) {
                uint32_t r0, r1, r2, r3;
                LDSM4(r0, r1, r2, r3, bb + (t * 16 + brow) * SA_BYTES + bk + k * 32);
                MMA16816(c[0][2 * t],     a0, a1, a2, a3, r0, r1);
                MMA16816(c[0][2 * t + 1], a0, a1, a2, a3, r2, r3);
                MMA16816(c[1][2 * t],     a4, a5, a6, a7, r0, r1);
                MMA16816(c[1][2 * t + 1], a4, a5, a6, a7, r2, r3);
            }
        }

        const float* snh = nhbuf[buf];
        const int cb = s * NSUB;
#pragma unroll
        for (int j = 0; j < 8; j++) {
            const int lc = j * 8 + 2 * (lane & 3);
            const float nh0 = snh[lc], nh1 = snh[lc + 1];
            const int gi = cb + lc;
            upd(b1r[0], b2r[0], i1r[0], c[0][j][0] + nh0, gi);
            upd(b1r[0], b2r[0], i1r[0], c[0][j][1] + nh1, gi + 1);
            upd(b1r[1], b2r[1], i1r[1], c[0][j][2] + nh0, gi);
            upd(b1r[1], b2r[1], i1r[1], c[0][j][3] + nh1, gi + 1);
            upd(b1r[2], b2r[2], i1r[2], c[1][j][0] + nh0, gi);
            upd(b1r[2], b2r[2], i1r[2], c[1][j][1] + nh1, gi + 1);
            upd(b1r[3], b2r[3], i1r[3], c[1][j][2] + nh0, gi);
            upd(b1r[3], b2r[3], i1r[3], c[1][j][3] + nh1, gi + 1);
        }

        if (s + 1 < NSUBS) {
            CP_WAIT0();
            __syncthreads();
        }
    }

#pragma unroll
    for (int r = 0; r < 4; r++) {
        mergepair(b1r[r], b2r[r], i1r[r], 1);
        mergepair(b1r[r], b2r[r], i1r[r], 2);
    }

    if ((lane & 3) == 0) {
        const int base = row0blk + wid * 32 + (lane >> 2);
        const int rofs[4] = { 0, 8, 16, 24 };
#pragma unroll
        for (int r = 0; r < 4; r++) {
            const int row = base + rofs[r];
            g_bi[row] = i1r[r];
            if (b1r[r] - b2r[r] < THRESH) {
                g_bm[row] = 0ull;                 // init packed-max slot
                int p = atomicAdd(&g_rcnt, 1);
                g_rlist[p] = row;
            }
        }
    }
}

// ---------------------------------------------------------------------------
// Rescue: exact fp32 rescan, task = (flagged row, 256-code chunk).
// 8 tasks/row, grid-stride over cnt*8 tasks; cross-chunk winner selected by
// atomicMax on monotone-packed (score, ~idx) u64 (max score, then min idx).
// ---------------------------------------------------------------------------
#define RES_CHUNK  256
#define RES_BLOCKS 148
__global__ void __launch_bounds__(256)
vq_rescue_kernel(const float* __restrict__ inp, const float* __restrict__ emb) {
    const int lane  = threadIdx.x & 31;
    const int gw    = (blockIdx.x * blockDim.x + threadIdx.x) >> 5;
    const int nw    = RES_BLOCKS * 256 / 32;
    const int ntask = g_rcnt * (KTOT / RES_CHUNK);

    for (int t = gw; t < ntask; t += nw) {
        const int row = g_rlist[t >> 3];
        const int k0  = (t & 7) * RES_CHUNK;

        float4 x[16];
        const float4* xr = reinterpret_cast<const float4*>(inp + (size_t)row * D);
#pragma unroll
        for (int j = 0; j < 16; j++) x[j] = xr[j];

        unsigned long long key = 0ull;
        for (int k = k0 + lane; k < k0 + RES_CHUNK; k += 32) {
            const float4* er = reinterpret_cast<const float4*>(emb + (size_t)k * D);
            float d0 = 0.f, d1 = 0.f, d2 = 0.f, d3 = 0.f;
#pragma unroll
            for (int j = 0; j < 16; j++) {
                float4 e = er[j];
                d0 = fmaf(x[j].x, e.x, d0);
                d1 = fmaf(x[j].y, e.y, d1);
                d2 = fmaf(x[j].z, e.z, d2);
                d3 = fmaf(x[j].w, e.w, d3);
            }
            float sc = ((d0 + d1) + (d2 + d3)) + g_nh[k];
            unsigned u = __float_as_uint(sc);
            u = (u & 0x80000000u) ? ~u : (u | 0x80000000u);   // monotone map
            unsigned long long kk =
                ((unsigned long long)u << 32) | (unsigned)(~k);
            key = (kk > key) ? kk : key;
        }
#pragma unroll
        for (int m = 16; m >= 1; m >>= 1) {
            unsigned long long ok = __shfl_xor_sync(0xffffffffu, key, m);
            key = (ok > key) ? ok : key;
        }
        if (lane == 0) atomicMax(&g_bm[row], key);
    }
}

// Unpack rescue winners back into g_bi (grid-stride over flag list)
__global__ void __launch_bounds__(256)
vq_unpack_kernel() {
    const int cnt = g_rcnt;
    for (int i = blockIdx.x * blockDim.x + threadIdx.x; i < cnt;
         i += gridDim.x * blockDim.x) {
        const int row = g_rlist[i];
        g_bi[row] = (int)(~(unsigned)(g_bm[row] & 0xFFFFFFFFull)) & (KTOT - 1);
    }
}

// ---------------------------------------------------------------------------
// Combine: emit all three outputs, fully coalesced (16 threads per row)
// ---------------------------------------------------------------------------
__global__ void __launch_bounds__(256)
vq_combine_kernel(const float* __restrict__ inp,
                  const float* __restrict__ emb,
                  float* __restrict__ out) {
    const int t   = blockIdx.x * blockDim.x + threadIdx.x;   // NROWS*16
    const int row = t >> 4;
    const int c   = t & 15;
    const int bi  = g_bi[row];

    const float4 qv = reinterpret_cast<const float4*>(emb + (size_t)bi * D)[c];
    reinterpret_cast<float4*>(out + (size_t)row * D)[c] = qv;

    const float4 xi = reinterpret_cast<const float4*>(inp + (size_t)row * D)[c];
    reinterpret_cast<float4*>(out + OFF_FLAT + (size_t)row * D)[c] = xi;

    if (c == 0) out[OFF_IDX + row] = (float)bi;
}

// ---------------------------------------------------------------------------
extern "C" void kernel_launch(void* const* d_in, const int* in_sizes, int n_in,
                              void* d_out, int out_size) {
    const float* inp = (const float*)d_in[0];   // [64,32,32,64] fp32
    const float* emb = (const float*)d_in[1];   // [2048,64]     fp32
    float* out = (float*)d_out;

    static int smem_set = 0;
    if (!smem_set) {
        cudaFuncSetAttribute(vq_mma_kernel,
                             cudaFuncAttributeMaxDynamicSharedMemorySize, SMEM_TOTAL);
        smem_set = 1;
    }

    vq_split_e<<<KTOT * 32 / 256, 256>>>(emb);
    vq_nh_kernel<<<(KTOT + 255) / 256, 256>>>(emb);
    vq_mma_kernel<<<NBLOCKS, 256, SMEM_TOTAL>>>(inp);
    vq_rescue_kernel<<<RES_BLOCKS, 256>>>(inp, emb);
    vq_unpack_kernel<<<64, 256>>>();
    vq_combine_kernel<<<NROWS * 16 / 256, 256>>>(inp, emb, out);
}